// round 1
// baseline (speedup 1.0000x reference)
#include <cuda_runtime.h>
#include <cuda_bf16.h>
#include <math.h>

// Problem constants
#define BATCH   2
#define SEQ     2048
#define DMODEL  1024
#define NHEADS  16
#define DHEAD   64
#define MROWS   (BATCH*SEQ)          // 4096
#define SCALE   0.125f               // DHEAD^-0.5

// -------- scratch (device globals; no cudaMalloc allowed) --------
__device__ float g_q[MROWS * DMODEL];
__device__ float g_k[MROWS * DMODEL];
__device__ float g_v[MROWS * DMODEL];
__device__ float g_ctx[MROWS * DMODEL];
__device__ float g_rc[SEQ * (DHEAD/2)];
__device__ float g_rs[SEQ * (DHEAD/2)];

// =============================================================
// RoPE tables: cos/sin[s][p], p = 0..31, inv_freq = 10000^(-2p/64)
// =============================================================
__global__ void rope_table_kernel() {
    int t = blockIdx.x;      // 0..2047
    int i = threadIdx.x;     // 0..31
    float inv = powf(10000.0f, -(2.0f * (float)i) / 64.0f);
    float ang = (float)t * inv;
    g_rc[t * 32 + i] = cosf(ang);
    g_rs[t * 32 + i] = sinf(ang);
}

// =============================================================
// SGEMM 128x128x8, 256 threads, 8x8 per-thread tile.
// C[M,N] = A[M,K] @ W[K,N] + bias, optional fused RoPE epilogue.
// M=4096, N=K=1024 fixed.
// =============================================================
__global__ __launch_bounds__(256)
void gemm_bias_rope_kernel(const float* __restrict__ A,
                           const float* __restrict__ W,
                           const float* __restrict__ bias,
                           float* __restrict__ C,
                           int applyRope)
{
    const int N = DMODEL, K = DMODEL;
    __shared__ float As[8][128];
    __shared__ float Bs[8][128];

    int tid  = threadIdx.x;
    int row0 = blockIdx.y * 128;
    int col0 = blockIdx.x * 128;
    int ty = tid >> 4;          // 0..15
    int tx = tid & 15;          // 0..15

    float acc[8][8];
    #pragma unroll
    for (int i = 0; i < 8; i++)
        #pragma unroll
        for (int j = 0; j < 8; j++) acc[i][j] = 0.f;

    int ar = tid >> 1;              // 0..127 (A tile row)
    int ak = (tid & 1) * 4;         // 0 or 4
    int bk = tid >> 5;              // 0..7   (B tile k-row)
    int bn = (tid & 31) * 4;        // 0..124

    const float* Aptr = A + (size_t)(row0 + ar) * K + ak;
    const float* Wptr = W + (size_t)bk * N + col0 + bn;

    for (int kt = 0; kt < K; kt += 8) {
        float4 av = *(const float4*)(Aptr + kt);
        float4 bv = *(const float4*)(Wptr + (size_t)kt * N);
        __syncthreads();   // prior compute finished before overwrite
        As[ak + 0][ar] = av.x;
        As[ak + 1][ar] = av.y;
        As[ak + 2][ar] = av.z;
        As[ak + 3][ar] = av.w;
        *(float4*)&Bs[bk][bn] = bv;
        __syncthreads();

        #pragma unroll
        for (int kk = 0; kk < 8; kk++) {
            float a[8], b[8];
            *(float4*)(a)     = *(float4*)&As[kk][ty * 8];
            *(float4*)(a + 4) = *(float4*)&As[kk][ty * 8 + 4];
            *(float4*)(b)     = *(float4*)&Bs[kk][tx * 8];
            *(float4*)(b + 4) = *(float4*)&Bs[kk][tx * 8 + 4];
            #pragma unroll
            for (int i = 0; i < 8; i++)
                #pragma unroll
                for (int j = 0; j < 8; j++)
                    acc[i][j] = fmaf(a[i], b[j], acc[i][j]);
        }
    }

    // epilogue: bias (+ RoPE), write two float4 per row
    float bvals[8];
    *(float4*)(bvals)     = *(const float4*)(bias + col0 + tx * 8);
    *(float4*)(bvals + 4) = *(const float4*)(bias + col0 + tx * 8 + 4);

    int pbase = ((tx * 8) & 63) >> 1;   // pair index base within head (0..28, step 4)

    #pragma unroll
    for (int i = 0; i < 8; i++) {
        int row = row0 + ty * 8 + i;
        float out[8];
        if (applyRope) {
            int s = row & (SEQ - 1);
            const float* crow = g_rc + s * 32;
            const float* srow = g_rs + s * 32;
            #pragma unroll
            for (int p = 0; p < 4; p++) {
                float xr = acc[i][2 * p]     + bvals[2 * p];
                float xi = acc[i][2 * p + 1] + bvals[2 * p + 1];
                float c  = crow[pbase + p];
                float sn = srow[pbase + p];
                out[2 * p]     = xr * c - xi * sn;
                out[2 * p + 1] = xr * sn + xi * c;
            }
        } else {
            #pragma unroll
            for (int j = 0; j < 8; j++) out[j] = acc[i][j] + bvals[j];
        }
        float* Cp = C + (size_t)row * N + col0 + tx * 8;
        *(float4*)(Cp)     = *(float4*)(out);
        *(float4*)(Cp + 4) = *(float4*)(out + 4);
    }
}

// =============================================================
// Flash attention fp32. 64 q-rows x 64 kv-rows tiles, dh=64.
// grid = (32 q-blocks, 32 bh). 256 threads, 4x4 O tile/thread.
// =============================================================
__global__ __launch_bounds__(256)
void flash_kernel()
{
    constexpr int P = 68;            // padded row stride (floats)
    extern __shared__ float sm[];
    float* Qs  = sm;                 // [64][P]  Qs[r*P + d]
    float* Kt  = sm + 64 * P;        // [d][c]   Kt[d*P + c]   (transposed)
    float* Vs  = sm + 2 * 64 * P;    // [kv][d]  Vs[kk*P + c]
    float* Ss  = sm + 3 * 64 * P;    // [r][c]   scores then probs
    float* ms  = sm + 4 * 64 * P;    // [64] running max
    float* ls  = ms + 64;            // [64] running sum
    float* scl = ls + 64;            // [64] rescale factor

    int tid = threadIdx.x;
    int iq  = blockIdx.x;            // q block 0..31
    int bh  = blockIdx.y;            // 0..31
    int b   = bh >> 4;
    int h   = bh & 15;

    const size_t base = (size_t)(b * SEQ) * DMODEL + h * DHEAD;
    const float* Qg = g_q + base + (size_t)iq * 64 * DMODEL;

    int ty = tid >> 4, tx = tid & 15;
    int r0 = ty * 4, c0 = tx * 4;

    // load Q tile (coalesced float4)
    #pragma unroll
    for (int i = 0; i < 4; i++) {
        int f  = tid + 256 * i;
        int r  = f >> 4;
        int c4 = (f & 15) * 4;
        *(float4*)&Qs[r * P + c4] = *(const float4*)(Qg + (size_t)r * DMODEL + c4);
    }
    if (tid < 64) { ms[tid] = -1e30f; ls[tid] = 0.f; }

    float o[4][4];
    #pragma unroll
    for (int i = 0; i < 4; i++)
        #pragma unroll
        for (int j = 0; j < 4; j++) o[i][j] = 0.f;

    __syncthreads();

    for (int jb = 0; jb <= iq; jb++) {
        const float* Kg = g_k + base + (size_t)jb * 64 * DMODEL;
        const float* Vg = g_v + base + (size_t)jb * 64 * DMODEL;

        // load K (transposed into Kt) and V (natural)
        #pragma unroll
        for (int i = 0; i < 4; i++) {
            int f  = tid + 256 * i;
            int r  = f >> 4;
            int c4 = (f & 15) * 4;
            float4 kv4 = *(const float4*)(Kg + (size_t)r * DMODEL + c4);
            Kt[(c4 + 0) * P + r] = kv4.x;
            Kt[(c4 + 1) * P + r] = kv4.y;
            Kt[(c4 + 2) * P + r] = kv4.z;
            Kt[(c4 + 3) * P + r] = kv4.w;
            *(float4*)&Vs[r * P + c4] = *(const float4*)(Vg + (size_t)r * DMODEL + c4);
        }
        __syncthreads();

        // S = Q K^T * scale
        float acc[4][4];
        #pragma unroll
        for (int i = 0; i < 4; i++)
            #pragma unroll
            for (int j = 0; j < 4; j++) acc[i][j] = 0.f;

        for (int d = 0; d < 64; d++) {
            float qa[4];
            #pragma unroll
            for (int i = 0; i < 4; i++) qa[i] = Qs[(r0 + i) * P + d];
            float4 kb = *(float4*)&Kt[d * P + c0];
            #pragma unroll
            for (int i = 0; i < 4; i++) {
                acc[i][0] = fmaf(qa[i], kb.x, acc[i][0]);
                acc[i][1] = fmaf(qa[i], kb.y, acc[i][1]);
                acc[i][2] = fmaf(qa[i], kb.z, acc[i][2]);
                acc[i][3] = fmaf(qa[i], kb.w, acc[i][3]);
            }
        }
        #pragma unroll
        for (int i = 0; i < 4; i++)
            #pragma unroll
            for (int j = 0; j < 4; j++)
                Ss[(r0 + i) * P + c0 + j] = acc[i][j] * SCALE;
        __syncthreads();

        // online softmax (one thread per row)
        if (tid < 64) {
            int r  = tid;
            int nv = (jb == iq) ? (r + 1) : 64;   // causal valid count
            float mold = ms[r];
            float mx = mold;
            for (int c = 0; c < nv; c++) mx = fmaxf(mx, Ss[r * P + c]);
            float sum = 0.f;
            for (int c = 0; c < 64; c++) {
                float pv = (c < nv) ? __expf(Ss[r * P + c] - mx) : 0.f;
                Ss[r * P + c] = pv;
                sum += pv;
            }
            float fct = __expf(mold - mx);
            ls[r] = ls[r] * fct + sum;
            ms[r] = mx;
            scl[r] = fct;
        }
        __syncthreads();

        // rescale O, then O += P @ V
        #pragma unroll
        for (int i = 0; i < 4; i++) {
            float fct = scl[r0 + i];
            #pragma unroll
            for (int j = 0; j < 4; j++) o[i][j] *= fct;
        }
        for (int d2 = 0; d2 < 64; d2++) {
            float pa[4];
            #pragma unroll
            for (int i = 0; i < 4; i++) pa[i] = Ss[(r0 + i) * P + d2];
            float4 vb = *(float4*)&Vs[d2 * P + c0];
            #pragma unroll
            for (int i = 0; i < 4; i++) {
                o[i][0] = fmaf(pa[i], vb.x, o[i][0]);
                o[i][1] = fmaf(pa[i], vb.y, o[i][1]);
                o[i][2] = fmaf(pa[i], vb.z, o[i][2]);
                o[i][3] = fmaf(pa[i], vb.w, o[i][3]);
            }
        }
        __syncthreads();   // protect Kt/Vs/Ss before next iteration
    }

    // normalize and write ctx
    #pragma unroll
    for (int i = 0; i < 4; i++) {
        float invl = 1.f / ls[r0 + i];
        int row = iq * 64 + r0 + i;
        float4 ov;
        ov.x = o[i][0] * invl;
        ov.y = o[i][1] * invl;
        ov.z = o[i][2] * invl;
        ov.w = o[i][3] * invl;
        *(float4*)(g_ctx + (size_t)(b * SEQ + row) * DMODEL + h * DHEAD + c0) = ov;
    }
}

// =============================================================
// launch
// =============================================================
extern "C" void kernel_launch(void* const* d_in, const int* in_sizes, int n_in,
                              void* d_out, int out_size)
{
    const float* x  = (const float*)d_in[0];
    const float* Wq = (const float*)d_in[1];
    const float* bq = (const float*)d_in[2];
    const float* Wk = (const float*)d_in[3];
    const float* bk = (const float*)d_in[4];
    const float* Wv = (const float*)d_in[5];
    const float* bv = (const float*)d_in[6];
    const float* Wo = (const float*)d_in[7];
    const float* bo = (const float*)d_in[8];
    float* out = (float*)d_out;

    float *pq, *pk, *pv, *pctx;
    cudaGetSymbolAddress((void**)&pq,   g_q);
    cudaGetSymbolAddress((void**)&pk,   g_k);
    cudaGetSymbolAddress((void**)&pv,   g_v);
    cudaGetSymbolAddress((void**)&pctx, g_ctx);

    // raise dynamic smem limit for flash (idempotent, cheap)
    const int flashSmem = (4 * 64 * 68 + 3 * 64) * (int)sizeof(float); // 70400 B
    cudaFuncSetAttribute(flash_kernel,
                         cudaFuncAttributeMaxDynamicSharedMemorySize, flashSmem);

    // 1) rope tables
    rope_table_kernel<<<SEQ, 32>>>();

    // 2) QKV projections (+RoPE on q,k)
    dim3 ggrid(DMODEL / 128, MROWS / 128);   // (8, 32)
    gemm_bias_rope_kernel<<<ggrid, 256>>>(x, Wq, bq, pq, 1);
    gemm_bias_rope_kernel<<<ggrid, 256>>>(x, Wk, bk, pk, 1);
    gemm_bias_rope_kernel<<<ggrid, 256>>>(x, Wv, bv, pv, 0);

    // 3) causal flash attention
    dim3 fgrid(SEQ / 64, BATCH * NHEADS);    // (32, 32)
    flash_kernel<<<fgrid, 256, flashSmem>>>();

    // 4) output projection
    gemm_bias_rope_kernel<<<ggrid, 256>>>(pctx, Wo, bo, out, 0);
}

// round 4
// speedup vs baseline: 1.4948x; 1.4948x over previous
#include <cuda_runtime.h>
#include <cuda_bf16.h>
#include <math.h>
#include <stdint.h>

// ---------------- problem constants ----------------
#define BATCH   2
#define SEQ     2048
#define DMODEL  1024
#define NHEADS  16
#define DHEAD   64
#define MROWS   (BATCH*SEQ)          // 4096
#define SCALE   0.125f

// ---------------- device scratch (no cudaMalloc allowed) ----------------
__device__ float g_q[MROWS * DMODEL];
__device__ float g_k[MROWS * DMODEL];
__device__ float g_v[MROWS * DMODEL];
__device__ float g_ctx[MROWS * DMODEL];
__device__ float g_rc[SEQ * 32];
__device__ float g_rs[SEQ * 32];
__device__ __nv_bfloat16 g_ah[MROWS * DMODEL];    // A hi split
__device__ __nv_bfloat16 g_al[MROWS * DMODEL];    // A lo split
__device__ __nv_bfloat16 g_wth[DMODEL * DMODEL];  // W^T hi split  [n][k]
__device__ __nv_bfloat16 g_wtl[DMODEL * DMODEL];  // W^T lo split  [n][k]

// ---------------- PTX helpers (sm_100 base-target safe) ----------------
__device__ __forceinline__ uint32_t smem_u32(const void* p) {
    uint32_t a;
    asm("{ .reg .u64 t; cvta.to.shared.u64 t, %1; cvt.u32.u64 %0, t; }" : "=r"(a) : "l"(p));
    return a;
}
__device__ __forceinline__ void cpasync16(uint32_t sdst, const void* gsrc) {
    asm volatile("cp.async.cg.shared.global [%0], [%1], 16;" :: "r"(sdst), "l"(gsrc));
}
__device__ __forceinline__ void cpasync_commit() {
    asm volatile("cp.async.commit_group;" ::: "memory");
}
__device__ __forceinline__ void ldsm4(uint32_t* d, uint32_t addr) {
    asm volatile("ldmatrix.sync.aligned.m8n8.x4.shared.b16 {%0,%1,%2,%3}, [%4];"
                 : "=r"(d[0]), "=r"(d[1]), "=r"(d[2]), "=r"(d[3]) : "r"(addr));
}
__device__ __forceinline__ void mma16816(float* c, const uint32_t* a, const uint32_t* b) {
    asm volatile(
        "mma.sync.aligned.m16n8k16.row.col.f32.bf16.bf16.f32 "
        "{%0,%1,%2,%3}, {%4,%5,%6,%7}, {%8,%9}, {%0,%1,%2,%3};"
        : "+f"(c[0]), "+f"(c[1]), "+f"(c[2]), "+f"(c[3])
        : "r"(a[0]), "r"(a[1]), "r"(a[2]), "r"(a[3]), "r"(b[0]), "r"(b[1]));
}
__device__ __forceinline__ uint32_t swz(uint32_t off) {   // 128B-row swizzle
    return off ^ ((off >> 3) & 0x70);
}

// ---------------- RoPE tables ----------------
__global__ void rope_table_kernel() {
    int t = blockIdx.x, i = threadIdx.x;
    float inv = powf(10000.0f, -(2.0f * (float)i) / 64.0f);
    float ang = (float)t * inv;
    g_rc[t * 32 + i] = cosf(ang);
    g_rs[t * 32 + i] = sinf(ang);
}

// ---------------- fp32 -> bf16 hi/lo split (elementwise) ----------------
__global__ __launch_bounds__(256)
void split_kernel(const float* __restrict__ src,
                  __nv_bfloat16* __restrict__ hi,
                  __nv_bfloat16* __restrict__ lo, int n) {
    int i = (blockIdx.x * 256 + threadIdx.x) * 4;
    if (i >= n) return;
    float4 v = *(const float4*)(src + i);
    float a[4] = {v.x, v.y, v.z, v.w};
    #pragma unroll
    for (int j = 0; j < 4; j++) {
        __nv_bfloat16 h = __float2bfloat16(a[j]);
        hi[i + j] = h;
        lo[i + j] = __float2bfloat16(a[j] - __bfloat162float(h));
    }
}

// ---------------- W[K][N] -> W^T hi/lo [N][K] bf16 ----------------
__global__ __launch_bounds__(256)
void tsplit_kernel(const float* __restrict__ W,
                   __nv_bfloat16* __restrict__ Th,
                   __nv_bfloat16* __restrict__ Tl) {
    __shared__ float t[32][33];
    int bn = blockIdx.x * 32;
    int bk = blockIdx.y * 32;
    int x = threadIdx.x, y0 = threadIdx.y;   // 32 x 8
    #pragma unroll
    for (int yy = y0; yy < 32; yy += 8)
        t[yy][x] = W[(size_t)(bk + yy) * DMODEL + bn + x];
    __syncthreads();
    #pragma unroll
    for (int yy = y0; yy < 32; yy += 8) {
        float v = t[x][yy];  // = W[bk+x][bn+yy]
        __nv_bfloat16 h = __float2bfloat16(v);
        size_t o = (size_t)(bn + yy) * DMODEL + bk + x;      // [n][k]
        Th[o] = h;
        Tl[o] = __float2bfloat16(v - __bfloat162float(h));
    }
}

// ---------------- mma.sync bf16-split GEMM ----------------
// C[4096,1024] = (Ah+Al) @ (Bh+Bl)^T + bias (+RoPE)
// CTA 128x128, 8 warps (warp tile 64x32), K-chunk 64, double-buffered cp.async.
#define TILE_B    16384                   // one 128x64 bf16 buffer (128B rows)
#define STAGE_B   (4 * TILE_B)            // Ah,Al,Bh,Bl
#define SM_GEMM_TOTAL (2 * STAGE_B)       // 131072

__global__ __launch_bounds__(256)
void gemm_mma_kernel(const __nv_bfloat16* __restrict__ Ah,
                     const __nv_bfloat16* __restrict__ Al,
                     const __nv_bfloat16* __restrict__ Bh,
                     const __nv_bfloat16* __restrict__ Bl,
                     const float* __restrict__ bias,
                     float* __restrict__ C,
                     int applyRope)
{
    extern __shared__ char smem[];
    uint32_t sb = smem_u32(smem);
    int tid  = threadIdx.x;
    int wid  = tid >> 5;
    int lane = tid & 31;
    int row0 = blockIdx.y * 128;
    int col0 = blockIdx.x * 128;

    const __nv_bfloat16* srcAh = Ah + (size_t)row0 * DMODEL;
    const __nv_bfloat16* srcAl = Al + (size_t)row0 * DMODEL;
    const __nv_bfloat16* srcBh = Bh + (size_t)col0 * DMODEL;
    const __nv_bfloat16* srcBl = Bl + (size_t)col0 * DMODEL;

    // per-thread load pattern (same for all 4 buffers)
    // 1024 chunks of 16B per buffer; 4 iters of 256 threads
    int m0w = (wid & 1) * 64;        // warp m offset
    int n0w = (wid >> 1) * 32;       // warp n offset

    float acc[4][4][4];
    #pragma unroll
    for (int i = 0; i < 4; i++)
        #pragma unroll
        for (int j = 0; j < 4; j++)
            #pragma unroll
            for (int r = 0; r < 4; r++) acc[i][j][r] = 0.f;

    // ---- prefetch helper (inlined manually via loop) ----
    auto prefetch = [&](int s) {
        uint32_t base = sb + (uint32_t)(s & 1) * STAGE_B;
        int kc = s * 64;
        #pragma unroll
        for (int i = 0; i < 4; i++) {
            int flat = i * 256 + tid;      // 0..1023
            int r  = flat >> 3;            // row 0..127
            int ch = flat & 7;             // 16B chunk
            uint32_t sw = swz((uint32_t)(r * 128 + ch * 16));
            size_t go = (size_t)r * DMODEL + kc + ch * 8;
            cpasync16(base + 0 * TILE_B + sw, srcAh + go);
            cpasync16(base + 1 * TILE_B + sw, srcAl + go);
            cpasync16(base + 2 * TILE_B + sw, srcBh + go);
            cpasync16(base + 3 * TILE_B + sw, srcBl + go);
        }
        cpasync_commit();
    };

    prefetch(0);

    // ldmatrix lane addressing (constant per thread)
    int raA = (lane & 15);                 // row within 16-row a-tile
    int caA = (lane >> 4) * 16;            // 0 or 16 bytes (k half)
    int rbB = ((lane >> 4) << 3) + (lane & 7);   // row within 16-row b-pair
    int cbB = ((lane >> 3) & 1) * 16;

    for (int s = 0; s < 16; s++) {
        if (s < 15) {
            prefetch(s + 1);
            asm volatile("cp.async.wait_group 1;" ::: "memory");
        } else {
            asm volatile("cp.async.wait_group 0;" ::: "memory");
        }
        __syncthreads();

        uint32_t base = sb + (uint32_t)(s & 1) * STAGE_B;
        uint32_t bAh = base;
        uint32_t bAl = base + TILE_B;
        uint32_t bBh = base + 2 * TILE_B;
        uint32_t bBl = base + 3 * TILE_B;

        #pragma unroll
        for (int kk = 0; kk < 4; kk++) {
            int cb = kk * 32;
            uint32_t ah[4][4], al[4][4];
            #pragma unroll
            for (int i = 0; i < 4; i++) {
                uint32_t off = swz((uint32_t)((m0w + i * 16 + raA) * 128 + cb + caA));
                ldsm4(ah[i], bAh + off);
                ldsm4(al[i], bAl + off);
            }
            uint32_t bh[2][4], bl[2][4];   // each covers 2 n-tiles
            #pragma unroll
            for (int jp = 0; jp < 2; jp++) {
                uint32_t off = swz((uint32_t)((n0w + jp * 16 + rbB) * 128 + cb + cbB));
                ldsm4(bh[jp], bBh + off);
                ldsm4(bl[jp], bBl + off);
            }
            #pragma unroll
            for (int i = 0; i < 4; i++) {
                #pragma unroll
                for (int j = 0; j < 4; j++) {
                    const uint32_t* Bhf = &bh[j >> 1][(j & 1) * 2];
                    const uint32_t* Blf = &bl[j >> 1][(j & 1) * 2];
                    mma16816(acc[i][j], ah[i], Bhf);   // Ah*Bh
                    mma16816(acc[i][j], ah[i], Blf);   // Ah*Bl
                    mma16816(acc[i][j], al[i], Bhf);   // Al*Bh
                }
            }
        }
        __syncthreads();
    }

    // ---- epilogue: bias (+RoPE), direct register -> gmem ----
    #pragma unroll
    for (int i = 0; i < 4; i++) {
        int m_lo = row0 + m0w + i * 16 + (lane >> 2);
        int m_hi = m_lo + 8;
        int s_lo = m_lo & (SEQ - 1);
        int s_hi = m_hi & (SEQ - 1);
        #pragma unroll
        for (int j = 0; j < 4; j++) {
            int n = col0 + n0w + j * 8 + (lane & 3) * 2;
            float b0 = bias[n], b1 = bias[n + 1];
            float v0 = acc[i][j][0] + b0;
            float v1 = acc[i][j][1] + b1;
            float v2 = acc[i][j][2] + b0;
            float v3 = acc[i][j][3] + b1;
            if (applyRope) {
                int pi = (n & 63) >> 1;
                float c0 = g_rc[s_lo * 32 + pi], s0 = g_rs[s_lo * 32 + pi];
                float c1 = g_rc[s_hi * 32 + pi], s1 = g_rs[s_hi * 32 + pi];
                float t0 = v0 * c0 - v1 * s0;
                float t1 = v0 * s0 + v1 * c0;
                float t2 = v2 * c1 - v3 * s1;
                float t3 = v2 * s1 + v3 * c1;
                v0 = t0; v1 = t1; v2 = t2; v3 = t3;
            }
            *(float2*)(C + (size_t)m_lo * DMODEL + n) = make_float2(v0, v1);
            *(float2*)(C + (size_t)m_hi * DMODEL + n) = make_float2(v2, v3);
        }
    }
}

// ---------------- flash attention fp32 (unchanged, known-good) ----------------
__global__ __launch_bounds__(256)
void flash_kernel()
{
    constexpr int P = 68;
    extern __shared__ float sm[];
    float* Qs  = sm;
    float* Kt  = sm + 64 * P;
    float* Vs  = sm + 2 * 64 * P;
    float* Ss  = sm + 3 * 64 * P;
    float* ms  = sm + 4 * 64 * P;
    float* ls  = ms + 64;
    float* scl = ls + 64;

    int tid = threadIdx.x;
    int iq  = blockIdx.x;
    int bh  = blockIdx.y;
    int b   = bh >> 4;
    int h   = bh & 15;

    const size_t base = (size_t)(b * SEQ) * DMODEL + h * DHEAD;
    const float* Qg = g_q + base + (size_t)iq * 64 * DMODEL;

    int ty = tid >> 4, tx = tid & 15;
    int r0 = ty * 4, c0 = tx * 4;

    #pragma unroll
    for (int i = 0; i < 4; i++) {
        int f  = tid + 256 * i;
        int r  = f >> 4;
        int c4 = (f & 15) * 4;
        *(float4*)&Qs[r * P + c4] = *(const float4*)(Qg + (size_t)r * DMODEL + c4);
    }
    if (tid < 64) { ms[tid] = -1e30f; ls[tid] = 0.f; }

    float o[4][4];
    #pragma unroll
    for (int i = 0; i < 4; i++)
        #pragma unroll
        for (int j = 0; j < 4; j++) o[i][j] = 0.f;

    __syncthreads();

    for (int jb = 0; jb <= iq; jb++) {
        const float* Kg = g_k + base + (size_t)jb * 64 * DMODEL;
        const float* Vg = g_v + base + (size_t)jb * 64 * DMODEL;

        #pragma unroll
        for (int i = 0; i < 4; i++) {
            int f  = tid + 256 * i;
            int r  = f >> 4;
            int c4 = (f & 15) * 4;
            float4 kv4 = *(const float4*)(Kg + (size_t)r * DMODEL + c4);
            Kt[(c4 + 0) * P + r] = kv4.x;
            Kt[(c4 + 1) * P + r] = kv4.y;
            Kt[(c4 + 2) * P + r] = kv4.z;
            Kt[(c4 + 3) * P + r] = kv4.w;
            *(float4*)&Vs[r * P + c4] = *(const float4*)(Vg + (size_t)r * DMODEL + c4);
        }
        __syncthreads();

        float acc[4][4];
        #pragma unroll
        for (int i = 0; i < 4; i++)
            #pragma unroll
            for (int j = 0; j < 4; j++) acc[i][j] = 0.f;

        for (int d = 0; d < 64; d++) {
            float qa[4];
            #pragma unroll
            for (int i = 0; i < 4; i++) qa[i] = Qs[(r0 + i) * P + d];
            float4 kb = *(float4*)&Kt[d * P + c0];
            #pragma unroll
            for (int i = 0; i < 4; i++) {
                acc[i][0] = fmaf(qa[i], kb.x, acc[i][0]);
                acc[i][1] = fmaf(qa[i], kb.y, acc[i][1]);
                acc[i][2] = fmaf(qa[i], kb.z, acc[i][2]);
                acc[i][3] = fmaf(qa[i], kb.w, acc[i][3]);
            }
        }
        #pragma unroll
        for (int i = 0; i < 4; i++)
            #pragma unroll
            for (int j = 0; j < 4; j++)
                Ss[(r0 + i) * P + c0 + j] = acc[i][j] * SCALE;
        __syncthreads();

        if (tid < 64) {
            int r  = tid;
            int nv = (jb == iq) ? (r + 1) : 64;
            float mold = ms[r];
            float mx = mold;
            for (int c = 0; c < nv; c++) mx = fmaxf(mx, Ss[r * P + c]);
            float sum = 0.f;
            for (int c = 0; c < 64; c++) {
                float pv = (c < nv) ? __expf(Ss[r * P + c] - mx) : 0.f;
                Ss[r * P + c] = pv;
                sum += pv;
            }
            float fct = __expf(mold - mx);
            ls[r] = ls[r] * fct + sum;
            ms[r] = mx;
            scl[r] = fct;
        }
        __syncthreads();

        #pragma unroll
        for (int i = 0; i < 4; i++) {
            float fct = scl[r0 + i];
            #pragma unroll
            for (int j = 0; j < 4; j++) o[i][j] *= fct;
        }
        for (int d2 = 0; d2 < 64; d2++) {
            float pa[4];
            #pragma unroll
            for (int i = 0; i < 4; i++) pa[i] = Ss[(r0 + i) * P + d2];
            float4 vb = *(float4*)&Vs[d2 * P + c0];
            #pragma unroll
            for (int i = 0; i < 4; i++) {
                o[i][0] = fmaf(pa[i], vb.x, o[i][0]);
                o[i][1] = fmaf(pa[i], vb.y, o[i][1]);
                o[i][2] = fmaf(pa[i], vb.z, o[i][2]);
                o[i][3] = fmaf(pa[i], vb.w, o[i][3]);
            }
        }
        __syncthreads();
    }

    #pragma unroll
    for (int i = 0; i < 4; i++) {
        float invl = 1.f / ls[r0 + i];
        int row = iq * 64 + r0 + i;
        float4 ov;
        ov.x = o[i][0] * invl;
        ov.y = o[i][1] * invl;
        ov.z = o[i][2] * invl;
        ov.w = o[i][3] * invl;
        *(float4*)(g_ctx + (size_t)(b * SEQ + row) * DMODEL + h * DHEAD + c0) = ov;
    }
}

// ---------------- launch ----------------
extern "C" void kernel_launch(void* const* d_in, const int* in_sizes, int n_in,
                              void* d_out, int out_size)
{
    const float* x  = (const float*)d_in[0];
    const float* Wq = (const float*)d_in[1];
    const float* bq = (const float*)d_in[2];
    const float* Wk = (const float*)d_in[3];
    const float* bk = (const float*)d_in[4];
    const float* Wv = (const float*)d_in[5];
    const float* bv = (const float*)d_in[6];
    const float* Wo = (const float*)d_in[7];
    const float* bo = (const float*)d_in[8];
    float* out = (float*)d_out;

    float *pq, *pk, *pv, *pctx;
    __nv_bfloat16 *pah, *pal, *pwh, *pwl;
    cudaGetSymbolAddress((void**)&pq,   g_q);
    cudaGetSymbolAddress((void**)&pk,   g_k);
    cudaGetSymbolAddress((void**)&pv,   g_v);
    cudaGetSymbolAddress((void**)&pctx, g_ctx);
    cudaGetSymbolAddress((void**)&pah,  g_ah);
    cudaGetSymbolAddress((void**)&pal,  g_al);
    cudaGetSymbolAddress((void**)&pwh,  g_wth);
    cudaGetSymbolAddress((void**)&pwl,  g_wtl);

    const int flashSmem = (4 * 64 * 68 + 3 * 64) * (int)sizeof(float);
    cudaFuncSetAttribute(flash_kernel,
                         cudaFuncAttributeMaxDynamicSharedMemorySize, flashSmem);
    cudaFuncSetAttribute(gemm_mma_kernel,
                         cudaFuncAttributeMaxDynamicSharedMemorySize, SM_GEMM_TOTAL);

    dim3 ggrid(DMODEL / 128, MROWS / 128);   // (8, 32)
    dim3 tgrid(32, 32), tblk(32, 8);
    const int nA = MROWS * DMODEL;

    rope_table_kernel<<<SEQ, 32>>>();
    split_kernel<<<nA / 1024, 256>>>(x, pah, pal, nA);

    // Q
    tsplit_kernel<<<tgrid, tblk>>>(Wq, pwh, pwl);
    gemm_mma_kernel<<<ggrid, 256, SM_GEMM_TOTAL>>>(pah, pal, pwh, pwl, bq, pq, 1);
    // K
    tsplit_kernel<<<tgrid, tblk>>>(Wk, pwh, pwl);
    gemm_mma_kernel<<<ggrid, 256, SM_GEMM_TOTAL>>>(pah, pal, pwh, pwl, bk, pk, 1);
    // V
    tsplit_kernel<<<tgrid, tblk>>>(Wv, pwh, pwl);
    gemm_mma_kernel<<<ggrid, 256, SM_GEMM_TOTAL>>>(pah, pal, pwh, pwl, bv, pv, 0);

    // attention
    dim3 fgrid(SEQ / 64, BATCH * NHEADS);
    flash_kernel<<<fgrid, 256, flashSmem>>>();

    // O projection
    split_kernel<<<nA / 1024, 256>>>(pctx, pah, pal, nA);
    tsplit_kernel<<<tgrid, tblk>>>(Wo, pwh, pwl);
    gemm_mma_kernel<<<ggrid, 256, SM_GEMM_TOTAL>>>(pah, pal, pwh, pwl, bo, out, 0);
}

// round 5
// speedup vs baseline: 2.9965x; 2.0046x over previous
#include <cuda_runtime.h>
#include <cuda_bf16.h>
#include <math.h>
#include <stdint.h>

// ---------------- problem constants ----------------
#define BATCH   2
#define SEQ     2048
#define DMODEL  1024
#define NHEADS  16
#define DHEAD   64
#define MROWS   (BATCH*SEQ)          // 4096
#define SCALE   0.125f

// ---------------- device scratch ----------------
__device__ float g_rc[SEQ * 32];
__device__ float g_rs[SEQ * 32];
__device__ __nv_bfloat16 g_ah[MROWS * DMODEL];    // A hi (x, then ctx)
__device__ __nv_bfloat16 g_al[MROWS * DMODEL];    // A lo
__device__ __nv_bfloat16 g_wth[DMODEL * DMODEL];  // W^T hi [n][k]
__device__ __nv_bfloat16 g_wtl[DMODEL * DMODEL];  // W^T lo [n][k]
__device__ __nv_bfloat16 g_qh[MROWS * DMODEL];
__device__ __nv_bfloat16 g_ql[MROWS * DMODEL];
__device__ __nv_bfloat16 g_kh[MROWS * DMODEL];
__device__ __nv_bfloat16 g_kl[MROWS * DMODEL];
__device__ __nv_bfloat16 g_vh[MROWS * DMODEL];
__device__ __nv_bfloat16 g_vl[MROWS * DMODEL];

// ---------------- PTX helpers (sm_100 base-target safe) ----------------
__device__ __forceinline__ uint32_t smem_u32(const void* p) {
    uint32_t a;
    asm("{ .reg .u64 t; cvta.to.shared.u64 t, %1; cvt.u32.u64 %0, t; }" : "=r"(a) : "l"(p));
    return a;
}
__device__ __forceinline__ void cpasync16(uint32_t sdst, const void* gsrc) {
    asm volatile("cp.async.cg.shared.global [%0], [%1], 16;" :: "r"(sdst), "l"(gsrc));
}
__device__ __forceinline__ void cpasync_commit() {
    asm volatile("cp.async.commit_group;" ::: "memory");
}
__device__ __forceinline__ void ldsm4(uint32_t* d, uint32_t addr) {
    asm volatile("ldmatrix.sync.aligned.m8n8.x4.shared.b16 {%0,%1,%2,%3}, [%4];"
                 : "=r"(d[0]), "=r"(d[1]), "=r"(d[2]), "=r"(d[3]) : "r"(addr));
}
__device__ __forceinline__ void ldsm4t(uint32_t* d, uint32_t addr) {
    asm volatile("ldmatrix.sync.aligned.m8n8.x4.trans.shared.b16 {%0,%1,%2,%3}, [%4];"
                 : "=r"(d[0]), "=r"(d[1]), "=r"(d[2]), "=r"(d[3]) : "r"(addr));
}
__device__ __forceinline__ void mma16816(float* c, const uint32_t* a, const uint32_t* b) {
    asm volatile(
        "mma.sync.aligned.m16n8k16.row.col.f32.bf16.bf16.f32 "
        "{%0,%1,%2,%3}, {%4,%5,%6,%7}, {%8,%9}, {%0,%1,%2,%3};"
        : "+f"(c[0]), "+f"(c[1]), "+f"(c[2]), "+f"(c[3])
        : "r"(a[0]), "r"(a[1]), "r"(a[2]), "r"(a[3]), "r"(b[0]), "r"(b[1]));
}
__device__ __forceinline__ uint32_t swz(uint32_t off) {   // 128B-row swizzle
    return off ^ ((off >> 3) & 0x70);
}
__device__ __forceinline__ uint32_t packbf2(float a, float b) {
    __nv_bfloat162 h = __floats2bfloat162_rn(a, b);   // x=a (low), y=b (high)
    return *(uint32_t*)&h;
}

// ---------------- RoPE tables ----------------
__global__ void rope_table_kernel() {
    int t = blockIdx.x, i = threadIdx.x;
    float inv = powf(10000.0f, -(2.0f * (float)i) / 64.0f);
    float ang = (float)t * inv;
    g_rc[t * 32 + i] = cosf(ang);
    g_rs[t * 32 + i] = sinf(ang);
}

// ---------------- fp32 -> bf16 hi/lo split ----------------
__global__ __launch_bounds__(256)
void split_kernel(const float* __restrict__ src,
                  __nv_bfloat16* __restrict__ hi,
                  __nv_bfloat16* __restrict__ lo, int n) {
    int i = (blockIdx.x * 256 + threadIdx.x) * 4;
    if (i >= n) return;
    float4 v = *(const float4*)(src + i);
    float a[4] = {v.x, v.y, v.z, v.w};
    #pragma unroll
    for (int j = 0; j < 4; j++) {
        __nv_bfloat16 h = __float2bfloat16(a[j]);
        hi[i + j] = h;
        lo[i + j] = __float2bfloat16(a[j] - __bfloat162float(h));
    }
}

// ---------------- W[K][N] -> W^T hi/lo [N][K] bf16 ----------------
__global__ __launch_bounds__(256)
void tsplit_kernel(const float* __restrict__ W,
                   __nv_bfloat16* __restrict__ Th,
                   __nv_bfloat16* __restrict__ Tl) {
    __shared__ float t[32][33];
    int bn = blockIdx.x * 32;
    int bk = blockIdx.y * 32;
    int x = threadIdx.x, y0 = threadIdx.y;   // 32 x 8
    #pragma unroll
    for (int yy = y0; yy < 32; yy += 8)
        t[yy][x] = W[(size_t)(bk + yy) * DMODEL + bn + x];
    __syncthreads();
    #pragma unroll
    for (int yy = y0; yy < 32; yy += 8) {
        float v = t[x][yy];
        __nv_bfloat16 h = __float2bfloat16(v);
        size_t o = (size_t)(bn + yy) * DMODEL + bk + x;
        Th[o] = h;
        Tl[o] = __float2bfloat16(v - __bfloat162float(h));
    }
}

// ---------------- mma.sync bf16-split GEMM ----------------
#define TILE_B    16384
#define STAGE_B   (4 * TILE_B)
#define SM_GEMM_TOTAL (2 * STAGE_B)       // 131072

__global__ __launch_bounds__(256)
void gemm_mma_kernel(const __nv_bfloat16* __restrict__ Ah,
                     const __nv_bfloat16* __restrict__ Al,
                     const __nv_bfloat16* __restrict__ Bh,
                     const __nv_bfloat16* __restrict__ Bl,
                     const float* __restrict__ bias,
                     float* __restrict__ Cf,
                     __nv_bfloat16* __restrict__ Ch,
                     __nv_bfloat16* __restrict__ Cl,
                     int applyRope, int splitOut)
{
    extern __shared__ char smem[];
    uint32_t sb = smem_u32(smem);
    int tid  = threadIdx.x;
    int wid  = tid >> 5;
    int lane = tid & 31;
    int row0 = blockIdx.y * 128;
    int col0 = blockIdx.x * 128;

    const __nv_bfloat16* srcAh = Ah + (size_t)row0 * DMODEL;
    const __nv_bfloat16* srcAl = Al + (size_t)row0 * DMODEL;
    const __nv_bfloat16* srcBh = Bh + (size_t)col0 * DMODEL;
    const __nv_bfloat16* srcBl = Bl + (size_t)col0 * DMODEL;

    int m0w = (wid & 1) * 64;
    int n0w = (wid >> 1) * 32;

    float acc[4][4][4];
    #pragma unroll
    for (int i = 0; i < 4; i++)
        #pragma unroll
        for (int j = 0; j < 4; j++)
            #pragma unroll
            for (int r = 0; r < 4; r++) acc[i][j][r] = 0.f;

    auto prefetch = [&](int s) {
        uint32_t base = sb + (uint32_t)(s & 1) * STAGE_B;
        int kc = s * 64;
        #pragma unroll
        for (int i = 0; i < 4; i++) {
            int flat = i * 256 + tid;
            int r  = flat >> 3;
            int ch = flat & 7;
            uint32_t sw = swz((uint32_t)(r * 128 + ch * 16));
            size_t go = (size_t)r * DMODEL + kc + ch * 8;
            cpasync16(base + 0 * TILE_B + sw, srcAh + go);
            cpasync16(base + 1 * TILE_B + sw, srcAl + go);
            cpasync16(base + 2 * TILE_B + sw, srcBh + go);
            cpasync16(base + 3 * TILE_B + sw, srcBl + go);
        }
        cpasync_commit();
    };

    prefetch(0);

    int raA = (lane & 15);
    int caA = (lane >> 4) * 16;
    int rbB = ((lane >> 4) << 3) + (lane & 7);
    int cbB = ((lane >> 3) & 1) * 16;

    for (int s = 0; s < 16; s++) {
        if (s < 15) {
            prefetch(s + 1);
            asm volatile("cp.async.wait_group 1;" ::: "memory");
        } else {
            asm volatile("cp.async.wait_group 0;" ::: "memory");
        }
        __syncthreads();

        uint32_t base = sb + (uint32_t)(s & 1) * STAGE_B;
        uint32_t bAh = base;
        uint32_t bAl = base + TILE_B;
        uint32_t bBh = base + 2 * TILE_B;
        uint32_t bBl = base + 3 * TILE_B;

        #pragma unroll
        for (int kk = 0; kk < 4; kk++) {
            int cb = kk * 32;
            uint32_t ah[4][4], al[4][4];
            #pragma unroll
            for (int i = 0; i < 4; i++) {
                uint32_t off = swz((uint32_t)((m0w + i * 16 + raA) * 128 + cb + caA));
                ldsm4(ah[i], bAh + off);
                ldsm4(al[i], bAl + off);
            }
            uint32_t bh[2][4], bl[2][4];
            #pragma unroll
            for (int jp = 0; jp < 2; jp++) {
                uint32_t off = swz((uint32_t)((n0w + jp * 16 + rbB) * 128 + cb + cbB));
                ldsm4(bh[jp], bBh + off);
                ldsm4(bl[jp], bBl + off);
            }
            #pragma unroll
            for (int i = 0; i < 4; i++) {
                #pragma unroll
                for (int j = 0; j < 4; j++) {
                    const uint32_t* Bhf = &bh[j >> 1][(j & 1) * 2];
                    const uint32_t* Blf = &bl[j >> 1][(j & 1) * 2];
                    mma16816(acc[i][j], ah[i], Bhf);
                    mma16816(acc[i][j], ah[i], Blf);
                    mma16816(acc[i][j], al[i], Bhf);
                }
            }
        }
        __syncthreads();
    }

    // ---- epilogue: bias (+RoPE), fp32 or bf16-split output ----
    #pragma unroll
    for (int i = 0; i < 4; i++) {
        int m_lo = row0 + m0w + i * 16 + (lane >> 2);
        int m_hi = m_lo + 8;
        int s_lo = m_lo & (SEQ - 1);
        int s_hi = m_hi & (SEQ - 1);
        #pragma unroll
        for (int j = 0; j < 4; j++) {
            int n = col0 + n0w + j * 8 + (lane & 3) * 2;
            float b0 = bias[n], b1 = bias[n + 1];
            float v0 = acc[i][j][0] + b0;
            float v1 = acc[i][j][1] + b1;
            float v2 = acc[i][j][2] + b0;
            float v3 = acc[i][j][3] + b1;
            if (applyRope) {
                int pi = (n & 63) >> 1;
                float c0 = g_rc[s_lo * 32 + pi], s0 = g_rs[s_lo * 32 + pi];
                float c1 = g_rc[s_hi * 32 + pi], s1 = g_rs[s_hi * 32 + pi];
                float t0 = v0 * c0 - v1 * s0;
                float t1 = v0 * s0 + v1 * c0;
                float t2 = v2 * c1 - v3 * s1;
                float t3 = v2 * s1 + v3 * c1;
                v0 = t0; v1 = t1; v2 = t2; v3 = t3;
            }
            if (splitOut) {
                __nv_bfloat162 h01 = __floats2bfloat162_rn(v0, v1);
                __nv_bfloat162 l01 = __floats2bfloat162_rn(
                    v0 - __bfloat162float(h01.x), v1 - __bfloat162float(h01.y));
                __nv_bfloat162 h23 = __floats2bfloat162_rn(v2, v3);
                __nv_bfloat162 l23 = __floats2bfloat162_rn(
                    v2 - __bfloat162float(h23.x), v3 - __bfloat162float(h23.y));
                *(__nv_bfloat162*)(Ch + (size_t)m_lo * DMODEL + n) = h01;
                *(__nv_bfloat162*)(Cl + (size_t)m_lo * DMODEL + n) = l01;
                *(__nv_bfloat162*)(Ch + (size_t)m_hi * DMODEL + n) = h23;
                *(__nv_bfloat162*)(Cl + (size_t)m_hi * DMODEL + n) = l23;
            } else {
                *(float2*)(Cf + (size_t)m_lo * DMODEL + n) = make_float2(v0, v1);
                *(float2*)(Cf + (size_t)m_hi * DMODEL + n) = make_float2(v2, v3);
            }
        }
    }
}

// ---------------- tensor-core flash attention (bf16 split, mma.sync) ----------------
// CTA: 128 q rows, 8 warps (16-row strip each), 64-kv blocks, double-buffered.
#define FSQ_H   0
#define FSQ_L   16384
#define FSKV    32768            // per stage: KH,KL,VH,VL each 8192
#define FKV_STAGE 32768
#define SM_FLASH_TOTAL (FSKV + 2 * FKV_STAGE)   // 98304

__global__ __launch_bounds__(256)
void flash_mma_kernel()
{
    extern __shared__ char smem[];
    uint32_t sb = smem_u32(smem);
    int tid  = threadIdx.x;
    int wid  = tid >> 5;
    int lane = tid & 31;
    int iq   = blockIdx.x;               // q block (128 rows)
    int bh   = blockIdx.y;
    int b    = bh >> 4;
    int h    = bh & 15;

    const size_t hb = (size_t)(b * SEQ) * DMODEL + h * DHEAD;
    const __nv_bfloat16* Qh = g_qh + hb + (size_t)iq * 128 * DMODEL;
    const __nv_bfloat16* Ql = g_ql + hb + (size_t)iq * 128 * DMODEL;

    // ---- Q load (both splits), committed with first KV group ----
    #pragma unroll
    for (int i = 0; i < 4; i++) {
        int flat = i * 256 + tid;        // 1024 chunks
        int r  = flat >> 3;
        int ch = flat & 7;
        uint32_t sw = swz((uint32_t)(r * 128 + ch * 16));
        size_t go = (size_t)r * DMODEL + ch * 8;
        cpasync16(sb + FSQ_H + sw, Qh + go);
        cpasync16(sb + FSQ_L + sw, Ql + go);
    }

    auto prefetch_kv = [&](int j) {
        uint32_t base = sb + FSKV + (uint32_t)(j & 1) * FKV_STAGE;
        const __nv_bfloat16* kh = g_kh + hb + (size_t)j * 64 * DMODEL;
        const __nv_bfloat16* kl = g_kl + hb + (size_t)j * 64 * DMODEL;
        const __nv_bfloat16* vh = g_vh + hb + (size_t)j * 64 * DMODEL;
        const __nv_bfloat16* vl = g_vl + hb + (size_t)j * 64 * DMODEL;
        #pragma unroll
        for (int i = 0; i < 2; i++) {
            int flat = i * 256 + tid;    // 512 chunks per buffer
            int r  = flat >> 3;
            int ch = flat & 7;
            uint32_t sw = swz((uint32_t)(r * 128 + ch * 16));
            size_t go = (size_t)r * DMODEL + ch * 8;
            cpasync16(base + 0     + sw, kh + go);
            cpasync16(base + 8192  + sw, kl + go);
            cpasync16(base + 16384 + sw, vh + go);
            cpasync16(base + 24576 + sw, vl + go);
        }
        cpasync_commit();
    };

    prefetch_kv(0);

    const int nblocks = (iq + 1) * 2;
    const int q0 = wid * 16;

    int raA = (lane & 15);
    int caA = (lane >> 4) * 16;
    int rbB = ((lane >> 4) << 3) + (lane & 7);
    int cbB = ((lane >> 3) & 1) * 16;
    int vrow = lane & 15;
    int vcol = (lane >> 4) * 16;

    const int grow0 = iq * 128 + q0 + (lane >> 2);   // global q row (elements c0,c1)
    const int grow1 = grow0 + 8;                     // (elements c2,c3)

    float o[8][4];
    #pragma unroll
    for (int j = 0; j < 8; j++)
        #pragma unroll
        for (int r = 0; r < 4; r++) o[j][r] = 0.f;
    float m0 = -1e30f, m1 = -1e30f, l0 = 0.f, l1 = 0.f;

    uint32_t qfh[4][4], qfl[4][4];
    bool qloaded = false;

    for (int jb = 0; jb < nblocks; jb++) {
        if (jb + 1 < nblocks) {
            prefetch_kv(jb + 1);
            asm volatile("cp.async.wait_group 1;" ::: "memory");
        } else {
            asm volatile("cp.async.wait_group 0;" ::: "memory");
        }
        __syncthreads();

        if (!qloaded) {
            #pragma unroll
            for (int kk = 0; kk < 4; kk++) {
                uint32_t off = swz((uint32_t)((q0 + raA) * 128 + kk * 32 + caA));
                ldsm4(qfh[kk], sb + FSQ_H + off);
                ldsm4(qfl[kk], sb + FSQ_L + off);
            }
            qloaded = true;
        }

        uint32_t kvb = sb + FSKV + (uint32_t)(jb & 1) * FKV_STAGE;

        // ---- S = (Qh+Ql)(Kh+Kl)^T (3-term) ----
        float s[8][4];
        #pragma unroll
        for (int j = 0; j < 8; j++)
            #pragma unroll
            for (int r = 0; r < 4; r++) s[j][r] = 0.f;

        #pragma unroll
        for (int kk = 0; kk < 4; kk++) {
            #pragma unroll
            for (int jp = 0; jp < 4; jp++) {
                uint32_t kh4[4], kl4[4];
                uint32_t off = swz((uint32_t)((jp * 16 + rbB) * 128 + kk * 32 + cbB));
                ldsm4(kh4, kvb + 0    + off);
                ldsm4(kl4, kvb + 8192 + off);
                #pragma unroll
                for (int hf = 0; hf < 2; hf++) {
                    int nt = jp * 2 + hf;
                    const uint32_t* Bh_ = &kh4[hf * 2];
                    const uint32_t* Bl_ = &kl4[hf * 2];
                    mma16816(s[nt], qfh[kk], Bh_);
                    mma16816(s[nt], qfh[kk], Bl_);
                    mma16816(s[nt], qfl[kk], Bh_);
                }
            }
        }

        // ---- scale + causal mask ----
        int kv0 = jb * 64;
        #pragma unroll
        for (int nt = 0; nt < 8; nt++)
            #pragma unroll
            for (int r = 0; r < 4; r++) s[nt][r] *= SCALE;
        if (kv0 + 63 > grow0) {
            #pragma unroll
            for (int nt = 0; nt < 8; nt++) {
                int c = kv0 + nt * 8 + (lane & 3) * 2;
                if (c > grow0)     s[nt][0] = -1e30f;
                if (c + 1 > grow0) s[nt][1] = -1e30f;
                if (c > grow1)     s[nt][2] = -1e30f;
                if (c + 1 > grow1) s[nt][3] = -1e30f;
            }
        }

        // ---- online softmax (register, quad shfl) ----
        float mxa = -1e30f, mxb = -1e30f;
        #pragma unroll
        for (int nt = 0; nt < 8; nt++) {
            mxa = fmaxf(mxa, fmaxf(s[nt][0], s[nt][1]));
            mxb = fmaxf(mxb, fmaxf(s[nt][2], s[nt][3]));
        }
        mxa = fmaxf(mxa, __shfl_xor_sync(0xffffffff, mxa, 1));
        mxa = fmaxf(mxa, __shfl_xor_sync(0xffffffff, mxa, 2));
        mxb = fmaxf(mxb, __shfl_xor_sync(0xffffffff, mxb, 1));
        mxb = fmaxf(mxb, __shfl_xor_sync(0xffffffff, mxb, 2));
        float mn0 = fmaxf(m0, mxa);
        float mn1 = fmaxf(m1, mxb);
        float al0 = __expf(m0 - mn0);
        float al1 = __expf(m1 - mn1);
        m0 = mn0; m1 = mn1;

        float p[8][4];
        float sum0 = 0.f, sum1 = 0.f;
        #pragma unroll
        for (int nt = 0; nt < 8; nt++) {
            p[nt][0] = __expf(s[nt][0] - mn0);
            p[nt][1] = __expf(s[nt][1] - mn0);
            p[nt][2] = __expf(s[nt][2] - mn1);
            p[nt][3] = __expf(s[nt][3] - mn1);
            sum0 += p[nt][0] + p[nt][1];
            sum1 += p[nt][2] + p[nt][3];
        }
        sum0 += __shfl_xor_sync(0xffffffff, sum0, 1);
        sum0 += __shfl_xor_sync(0xffffffff, sum0, 2);
        sum1 += __shfl_xor_sync(0xffffffff, sum1, 1);
        sum1 += __shfl_xor_sync(0xffffffff, sum1, 2);
        l0 = l0 * al0 + sum0;
        l1 = l1 * al1 + sum1;

        #pragma unroll
        for (int nt = 0; nt < 8; nt++) {
            o[nt][0] *= al0; o[nt][1] *= al0;
            o[nt][2] *= al1; o[nt][3] *= al1;
        }

        // ---- pack P into A-frags, hi/lo ----
        uint32_t pfh[4][4], pfl[4][4];
        #pragma unroll
        for (int t = 0; t < 4; t++) {
            int n0 = 2 * t, n1 = 2 * t + 1;
            float e[8] = {p[n0][0], p[n0][1], p[n0][2], p[n0][3],
                          p[n1][0], p[n1][1], p[n1][2], p[n1][3]};
            #pragma unroll
            for (int g = 0; g < 4; g++) {
                __nv_bfloat162 hh = __floats2bfloat162_rn(e[2*g], e[2*g+1]);
                pfh[t][g] = *(uint32_t*)&hh;
                __nv_bfloat162 ll = __floats2bfloat162_rn(
                    e[2*g]   - __bfloat162float(hh.x),
                    e[2*g+1] - __bfloat162float(hh.y));
                pfl[t][g] = *(uint32_t*)&ll;
            }
        }

        // ---- O += P @ V (3-term), V via ldmatrix.trans ----
        #pragma unroll
        for (int t = 0; t < 4; t++) {
            #pragma unroll
            for (int jp = 0; jp < 4; jp++) {
                uint32_t vh4[4], vl4[4];
                uint32_t off = swz((uint32_t)((t * 16 + vrow) * 128 + jp * 32 + vcol));
                ldsm4t(vh4, kvb + 16384 + off);
                ldsm4t(vl4, kvb + 24576 + off);
                #pragma unroll
                for (int hf = 0; hf < 2; hf++) {
                    int nt = jp * 2 + hf;
                    const uint32_t* Bh_ = &vh4[hf * 2];
                    const uint32_t* Bl_ = &vl4[hf * 2];
                    mma16816(o[nt], pfh[t], Bh_);
                    mma16816(o[nt], pfl[t], Bh_);
                    mma16816(o[nt], pfh[t], Bl_);
                }
            }
        }
        __syncthreads();
    }

    // ---- finalize: normalize, write ctx as bf16 hi/lo into g_ah/g_al ----
    float inv0 = 1.f / l0;
    float inv1 = 1.f / l1;
    size_t r0g = (size_t)(b * SEQ + grow0) * DMODEL + h * DHEAD;
    size_t r1g = (size_t)(b * SEQ + grow1) * DMODEL + h * DHEAD;
    #pragma unroll
    for (int nt = 0; nt < 8; nt++) {
        int c = nt * 8 + (lane & 3) * 2;
        float v0 = o[nt][0] * inv0, v1 = o[nt][1] * inv0;
        float v2 = o[nt][2] * inv1, v3 = o[nt][3] * inv1;
        __nv_bfloat162 h01 = __floats2bfloat162_rn(v0, v1);
        __nv_bfloat162 l01 = __floats2bfloat162_rn(
            v0 - __bfloat162float(h01.x), v1 - __bfloat162float(h01.y));
        __nv_bfloat162 h23 = __floats2bfloat162_rn(v2, v3);
        __nv_bfloat162 l23 = __floats2bfloat162_rn(
            v2 - __bfloat162float(h23.x), v3 - __bfloat162float(h23.y));
        *(__nv_bfloat162*)(g_ah + r0g + c) = h01;
        *(__nv_bfloat162*)(g_al + r0g + c) = l01;
        *(__nv_bfloat162*)(g_ah + r1g + c) = h23;
        *(__nv_bfloat162*)(g_al + r1g + c) = l23;
    }
}

// ---------------- launch ----------------
extern "C" void kernel_launch(void* const* d_in, const int* in_sizes, int n_in,
                              void* d_out, int out_size)
{
    const float* x  = (const float*)d_in[0];
    const float* Wq = (const float*)d_in[1];
    const float* bq = (const float*)d_in[2];
    const float* Wk = (const float*)d_in[3];
    const float* bk = (const float*)d_in[4];
    const float* Wv = (const float*)d_in[5];
    const float* bv = (const float*)d_in[6];
    const float* Wo = (const float*)d_in[7];
    const float* bo = (const float*)d_in[8];
    float* out = (float*)d_out;

    __nv_bfloat16 *pah, *pal, *pwh, *pwl, *pqh, *pql, *pkh, *pkl, *pvh, *pvl;
    cudaGetSymbolAddress((void**)&pah, g_ah);
    cudaGetSymbolAddress((void**)&pal, g_al);
    cudaGetSymbolAddress((void**)&pwh, g_wth);
    cudaGetSymbolAddress((void**)&pwl, g_wtl);
    cudaGetSymbolAddress((void**)&pqh, g_qh);
    cudaGetSymbolAddress((void**)&pql, g_ql);
    cudaGetSymbolAddress((void**)&pkh, g_kh);
    cudaGetSymbolAddress((void**)&pkl, g_kl);
    cudaGetSymbolAddress((void**)&pvh, g_vh);
    cudaGetSymbolAddress((void**)&pvl, g_vl);

    cudaFuncSetAttribute(gemm_mma_kernel,
                         cudaFuncAttributeMaxDynamicSharedMemorySize, SM_GEMM_TOTAL);
    cudaFuncSetAttribute(flash_mma_kernel,
                         cudaFuncAttributeMaxDynamicSharedMemorySize, SM_FLASH_TOTAL);

    dim3 ggrid(DMODEL / 128, MROWS / 128);   // (8, 32)
    dim3 tgrid(32, 32), tblk(32, 8);
    const int nA = MROWS * DMODEL;

    rope_table_kernel<<<SEQ, 32>>>();
    split_kernel<<<nA / 1024, 256>>>(x, pah, pal, nA);

    // Q
    tsplit_kernel<<<tgrid, tblk>>>(Wq, pwh, pwl);
    gemm_mma_kernel<<<ggrid, 256, SM_GEMM_TOTAL>>>(pah, pal, pwh, pwl, bq,
                                                   nullptr, pqh, pql, 1, 1);
    // K
    tsplit_kernel<<<tgrid, tblk>>>(Wk, pwh, pwl);
    gemm_mma_kernel<<<ggrid, 256, SM_GEMM_TOTAL>>>(pah, pal, pwh, pwl, bk,
                                                   nullptr, pkh, pkl, 1, 1);
    // V
    tsplit_kernel<<<tgrid, tblk>>>(Wv, pwh, pwl);
    gemm_mma_kernel<<<ggrid, 256, SM_GEMM_TOTAL>>>(pah, pal, pwh, pwl, bv,
                                                   nullptr, pvh, pvl, 0, 1);

    // attention (writes ctx hi/lo into g_ah/g_al)
    dim3 fgrid(SEQ / 128, BATCH * NHEADS);   // (16, 32)
    flash_mma_kernel<<<fgrid, 256, SM_FLASH_TOTAL>>>();

    // O projection (fp32 out)
    tsplit_kernel<<<tgrid, tblk>>>(Wo, pwh, pwl);
    gemm_mma_kernel<<<ggrid, 256, SM_GEMM_TOTAL>>>(pah, pal, pwh, pwl, bo,
                                                   out, nullptr, nullptr, 0, 0);
}